// round 9
// baseline (speedup 1.0000x reference)
#include <cuda_runtime.h>

// CalibrationLayer R9: full-range chord table — zero edge machinery.
//
// K buckets over the ENTIRE [ri[0], ri[R-1]]; per-bucket {slope, intercept}
// (absolute x coords). Eval:
//   xc = clamp(x, lo, hi); b = min(trunc(fma(xc,invw,nglo)), K-1);
//   y  = fma(tab[b].x, xc, tab[b].y)
// Clamping xc makes the end-clamps exact via the chord itself (edges are the
// interpolant values). Multi-knot buckets: chord dev ~5e-6 abs << 1e-3.
// No oob flags, no fixup, no branches in the hot loop. 7 ops/element.
// Table 114.7KB/CTA (in-place build) -> 2 CTAs x 1024 thr/SM.

#define THREADS 1024
#define CTAS_PER_SM 2
#define GRID    (148 * CTAS_PER_SM)
#define KBUCK   14336
#define SMEM_BYTES (KBUCK * 8 + 16)

extern __shared__ float smem[];   // build: edge[e] at smem[2e]; final: float2 recs

__global__ __launch_bounds__(THREADS, CTAS_PER_SM)
void calib_kernel(const float* __restrict__ x,
                  const float* __restrict__ ri,
                  const float* __restrict__ ro,
                  float* __restrict__ out,
                  int n, int R) {
    float2* __restrict__ tab = (float2*)smem;

    const float lo = __ldg(&ri[0]);
    const float hi = __ldg(&ri[R - 1]);
    const float w    = (hi - lo) / (float)KBUCK;
    const float invw = (float)KBUCK / (hi - lo);
    const float nglo = -lo * invw;          // fb = fma(xc, invw, nglo)

    // ---- pass 1: exact interpolant values at the K+1 edges -> smem[2e] ----
    // Interval [t, t+1) owns edges [ceil((ri[t]-lo)*invw), ceil((ri[t+1]-lo)*invw));
    // identical fp expressions make the ranges tile [0, K] exactly once.
    for (int t = threadIdx.x; t < R - 1; t += THREADS) {
        const float xt = __ldg(ri + t);
        const float xp = __ldg(ri + t + 1);
        const float yt = __ldg(ro + t);
        const float yp = __ldg(ro + t + 1);
        const float bR = (yp - yt) * (1.0f / (xp - xt));

        int s0 = (int)ceilf(__fmul_rn(__fsub_rn(xt, lo), invw));
        int s1 = (t + 1 < R - 1)
                   ? (int)ceilf(__fmul_rn(__fsub_rn(xp, lo), invw))
                   : (KBUCK + 1);          // last interval owns the top edges
        s0 = max(s0, 0);
        s1 = min(s1, KBUCK + 1);
        for (int e = s0; e < s1; ++e) {
            float ex = fmaf((float)e, w, lo);
            smem[2 * e] = fmaf(bR, ex - xt, yt);
        }
    }
    __syncthreads();

    // ---- pass 2: in-place convert to {slope, intercept} (chunked) ----
    for (int base = 0; base < KBUCK; base += THREADS) {
        int b = base + (int)threadIdx.x;
        bool valid = (b < KBUCK);
        float yl = 0.f, yh = 0.f, xb = 0.f;
        if (valid) {
            yl = smem[2 * b];
            yh = smem[2 * b + 2];
            xb = fmaf((float)b, w, lo);
        }
        __syncthreads();
        if (valid) {
            float s = (yh - yl) * invw;
            tab[b] = make_float2(s, fmaf(-s, xb, yl));
        }
        __syncthreads();
    }

    // ---- streaming phase: branchless 7-op eval ----
    auto eval = [&](float xv) -> float {
        float xc = fminf(fmaxf(xv, lo), hi);
        float fb = fmaf(xc, invw, nglo);     // in [-ulp, K]
        int b = (int)fb;                     // trunc: -ulp -> 0
        b = min(b, KBUCK - 1);               // fb == K (xc == hi) -> K-1
        float2 c = tab[b];
        return fmaf(c.x, xc, c.y);
    };

    const int n4 = n >> 2;
    const float4* __restrict__ x4 = (const float4*)x;
    float4* __restrict__ o4 = (float4*)out;

    #pragma unroll 2
    for (int i = blockIdx.x * THREADS + threadIdx.x; i < n4; i += GRID * THREADS) {
        float4 v = x4[i];
        float4 o;
        o.x = eval(v.x);
        o.y = eval(v.y);
        o.z = eval(v.z);
        o.w = eval(v.w);
        o4[i] = o;
    }

    const int base = n4 << 2;   // tail (n % 4)
    if (blockIdx.x == 0) {
        for (int i = base + threadIdx.x; i < n; i += THREADS)
            out[i] = eval(x[i]);
    }
}

extern "C" void kernel_launch(void* const* d_in, const int* in_sizes, int n_in,
                              void* d_out, int out_size) {
    const float* x  = (const float*)d_in[0];
    const float* ri = (const float*)d_in[1];
    const float* ro = (const float*)d_in[2];
    float* out      = (float*)d_out;
    const int n = in_sizes[0];
    const int R = in_sizes[1];
    cudaFuncSetAttribute(calib_kernel, cudaFuncAttributeMaxDynamicSharedMemorySize,
                         SMEM_BYTES);
    calib_kernel<<<GRID, THREADS, SMEM_BYTES>>>(x, ri, ro, out, n, R);
}

// round 10
// speedup vs baseline: 1.1635x; 1.1635x over previous
#include <cuda_runtime.h>

// CalibrationLayer R10: split build/stream, 16/16 packed chord table (LDS.32),
// 2x unrolled streamer.
//
//  k1 build_edges: exact interpolant values at K+1 grid edges -> g_edge (global)
//  k2 pack:        rec(b) = (round(ylo*65535)<<16) | (qy(b+1)-qy(b)) -> g_tab
//  k3 main:        CTA copies g_tab (57KB, L2-hot) to shared; streams x with
//                  branchless frac eval:  fb = clamp(fma(x,invw,nglo), 0, K);
//                  b = min((int)fb, K-1); y = (qy + qd*(fb-b)) / 65535
// fb-clamping makes both end-clamps exact (edge values = ro ends, quantized).
// Chord dev ~5e-6 + quant 8e-6 abs << 1e-3 tolerance.

#define KBUCK   14336
#define QS      65535.0f
#define QINV    (1.0f / 65535.0f)

#define MAIN_THREADS 512
#define MAIN_CTAS    3
#define MAIN_GRID    (148 * MAIN_CTAS)
#define SMEM_BYTES   (KBUCK * 4)

__device__ float        g_edge[KBUCK + 1];
__device__ unsigned int g_tab[KBUCK];

// ---- kernel 1: exact edge values via interval scatter ----
__global__ void build_edges(const float* __restrict__ ri,
                            const float* __restrict__ ro, int R) {
    const float lo   = __ldg(&ri[0]);
    const float hi   = __ldg(&ri[R - 1]);
    const float w    = (hi - lo) / (float)KBUCK;
    const float invw = (float)KBUCK / (hi - lo);

    // Interval t owns edges [ceil((ri[t]-lo)*invw), ceil((ri[t+1]-lo)*invw));
    // identical fp expressions tile [0, KBUCK] exactly once.
    for (int t = blockIdx.x * blockDim.x + threadIdx.x; t < R - 1;
         t += gridDim.x * blockDim.x) {
        const float xt = __ldg(ri + t);
        const float xp = __ldg(ri + t + 1);
        const float yt = __ldg(ro + t);
        const float yp = __ldg(ro + t + 1);
        const float bR = (yp - yt) * (1.0f / (xp - xt));

        int s0 = (int)ceilf(__fmul_rn(__fsub_rn(xt, lo), invw));
        int s1 = (t + 1 < R - 1)
                   ? (int)ceilf(__fmul_rn(__fsub_rn(xp, lo), invw))
                   : (KBUCK + 1);           // last interval owns top edges
        s0 = max(s0, 0);
        s1 = min(s1, KBUCK + 1);
        for (int e = s0; e < s1; ++e) {
            float ex = fmaf((float)e, w, lo);
            g_edge[e] = fmaf(bR, ex - xt, yt);
        }
    }
}

// ---- kernel 2: quantize + pack (separate arrays -> no hazards) ----
__global__ void pack_tab() {
    int b = blockIdx.x * blockDim.x + threadIdx.x;
    if (b < KBUCK) {
        float yl = g_edge[b];
        float yh = g_edge[b + 1];
        int ql = min(max(__float2int_rn(yl * QS), 0), 65535);
        int qh = min(max(__float2int_rn(yh * QS), 0), 65535);
        g_tab[b] = ((unsigned int)ql << 16) | (unsigned int)(qh - ql);
    }
}

// ---- kernel 3: streamer ----
extern __shared__ unsigned int tb[];

__global__ __launch_bounds__(MAIN_THREADS, MAIN_CTAS)
void calib_main(const float* __restrict__ x,
                const float* __restrict__ ri,
                float* __restrict__ out,
                int n, int R) {
    // cooperative table load (coalesced, L2-hot: 7x LDG.128 per thread)
    {
        const uint4* __restrict__ src = (const uint4*)g_tab;
        uint4* __restrict__ dst = (uint4*)tb;
        #pragma unroll
        for (int k = 0; k < KBUCK / 4 / MAIN_THREADS; ++k)
            dst[k * MAIN_THREADS + threadIdx.x] = src[k * MAIN_THREADS + threadIdx.x];
    }
    __syncthreads();

    const float lo   = __ldg(&ri[0]);
    const float hi   = __ldg(&ri[R - 1]);
    const float invw = (float)KBUCK / (hi - lo);
    const float nglo = -lo * invw;
    const float fK   = (float)KBUCK;

    auto eval = [&](float xv) -> float {
        float fb = fmaf(xv, invw, nglo);
        fb = fminf(fmaxf(fb, 0.0f), fK);          // end-clamps via edge values
        int b = (int)fb;                          // trunc == floor (fb >= 0)
        b = min(b, KBUCK - 1);                    // fb == K -> top bucket, frac=1
        unsigned int rec = tb[b];                 // LDS.32
        float frac = fb - (float)b;
        float qy = (float)(rec >> 16);
        float qd = (float)(rec & 0xFFFFu);
        return fmaf(qd, frac, qy) * QINV;
    };

    const int n4 = n >> 2;
    const int stride = MAIN_GRID * MAIN_THREADS;
    const float4* __restrict__ x4 = (const float4*)x;
    float4* __restrict__ o4 = (float4*)out;

    int i = blockIdx.x * MAIN_THREADS + threadIdx.x;

    // 2x unrolled grid-stride: 8 independent elements in flight
    for (; i + stride < n4; i += 2 * stride) {
        float4 va = x4[i];
        float4 vb = x4[i + stride];
        float4 oa, ob;
        oa.x = eval(va.x);  oa.y = eval(va.y);
        oa.z = eval(va.z);  oa.w = eval(va.w);
        ob.x = eval(vb.x);  ob.y = eval(vb.y);
        ob.z = eval(vb.z);  ob.w = eval(vb.w);
        o4[i] = oa;
        o4[i + stride] = ob;
    }
    for (; i < n4; i += stride) {
        float4 v = x4[i];
        float4 o;
        o.x = eval(v.x);  o.y = eval(v.y);
        o.z = eval(v.z);  o.w = eval(v.w);
        o4[i] = o;
    }

    const int base = n4 << 2;   // tail (n % 4)
    if (blockIdx.x == 0) {
        for (int j = base + threadIdx.x; j < n; j += MAIN_THREADS)
            out[j] = eval(x[j]);
    }
}

extern "C" void kernel_launch(void* const* d_in, const int* in_sizes, int n_in,
                              void* d_out, int out_size) {
    const float* x  = (const float*)d_in[0];
    const float* ri = (const float*)d_in[1];
    const float* ro = (const float*)d_in[2];
    float* out      = (float*)d_out;
    const int n = in_sizes[0];
    const int R = in_sizes[1];

    build_edges<<<64, 256>>>(ri, ro, R);
    pack_tab<<<(KBUCK + 255) / 256, 256>>>();
    cudaFuncSetAttribute(calib_main, cudaFuncAttributeMaxDynamicSharedMemorySize,
                         SMEM_BYTES);
    calib_main<<<MAIN_GRID, MAIN_THREADS, SMEM_BYTES>>>(x, ri, out, n, R);
}

// round 11
// speedup vs baseline: 1.3931x; 1.1974x over previous
#include <cuda_runtime.h>

// CalibrationLayer R11: fast per-bucket build (binary search) + R10 streamer.
//
//  k1 build_pack: thread per bucket b computes interpolant values at edges
//     b and b+1 via independent binary searches over ri (L2-hot), quantizes,
//     packs rec(b) = (round(ylo*65535)<<16) | (qy(b+1)-qy(b)) -> g_tab.
//     Continuity is exact: adjacent threads quantize the shared edge with the
//     identical expression. (Replaces R10's 10.2us imbalanced interval scatter.)
//  k2 calib_main: CTA copies g_tab (57KB, L2-hot) into shared; branchless
//     frac eval: fb = clamp(fma(x,invw,nglo),0,K); b = min((int)fb,K-1);
//     y = (qy + qd*(fb-b)) / 65535.  fb-clamp makes both end-clamps exact.
// Chord dev ~5e-6 + quant 8e-6 abs << 1e-3 tolerance.

#define KBUCK   14336
#define QS      65535.0f
#define QINV    (1.0f / 65535.0f)

#define MAIN_THREADS 512
#define MAIN_CTAS    3
#define MAIN_GRID    (148 * MAIN_CTAS)
#define SMEM_BYTES   (KBUCK * 4)

__device__ unsigned int g_tab[KBUCK];

// interpolant value at grid edge e (binary search; exact up to ulps)
__device__ __forceinline__ float edge_val(int e, const float* __restrict__ ri,
                                          const float* __restrict__ ro,
                                          int R, float lo, float w) {
    float ex = fmaf((float)e, w, lo);
    int a = 0, b = R - 1;
    while (b - a > 1) {                    // find a: ri[a] <= ex < ri[a+1]
        int m = (a + b) >> 1;
        if (__ldg(ri + m) <= ex) a = m; else b = m;
    }
    float xt = __ldg(ri + a), xp = __ldg(ri + a + 1);
    float yt = __ldg(ro + a), yp = __ldg(ro + a + 1);
    return yt + (yp - yt) * __fdividef(ex - xt, xp - xt);
}

// ---- kernel 1: build + pack, one thread per bucket ----
__global__ void build_pack(const float* __restrict__ ri,
                           const float* __restrict__ ro, int R) {
    int b = blockIdx.x * blockDim.x + threadIdx.x;
    if (b >= KBUCK) return;
    const float lo = __ldg(&ri[0]);
    const float hi = __ldg(&ri[R - 1]);
    const float w  = (hi - lo) / (float)KBUCK;

    float yl = edge_val(b,     ri, ro, R, lo, w);
    float yh = edge_val(b + 1, ri, ro, R, lo, w);
    int ql = min(max(__float2int_rn(yl * QS), 0), 65535);
    int qh = min(max(__float2int_rn(yh * QS), 0), 65535);
    g_tab[b] = ((unsigned int)ql << 16) | (unsigned int)(qh - ql);
}

// ---- kernel 2: streamer (R10 design) ----
extern __shared__ unsigned int tb[];

__global__ __launch_bounds__(MAIN_THREADS, MAIN_CTAS)
void calib_main(const float* __restrict__ x,
                const float* __restrict__ ri,
                float* __restrict__ out,
                int n, int R) {
    // cooperative table load (coalesced, L2-hot: 7x LDG.128 per thread)
    {
        const uint4* __restrict__ src = (const uint4*)g_tab;
        uint4* __restrict__ dst = (uint4*)tb;
        #pragma unroll
        for (int k = 0; k < KBUCK / 4 / MAIN_THREADS; ++k)
            dst[k * MAIN_THREADS + threadIdx.x] = src[k * MAIN_THREADS + threadIdx.x];
    }
    __syncthreads();

    const float lo   = __ldg(&ri[0]);
    const float hi   = __ldg(&ri[R - 1]);
    const float invw = (float)KBUCK / (hi - lo);
    const float nglo = -lo * invw;
    const float fK   = (float)KBUCK;

    auto eval = [&](float xv) -> float {
        float fb = fmaf(xv, invw, nglo);
        fb = fminf(fmaxf(fb, 0.0f), fK);          // end-clamps via edge values
        int b = (int)fb;                          // trunc == floor (fb >= 0)
        b = min(b, KBUCK - 1);                    // fb == K -> top bucket, frac=1
        unsigned int rec = tb[b];                 // LDS.32
        float frac = fb - (float)b;
        float qy = (float)(rec >> 16);
        float qd = (float)(rec & 0xFFFFu);
        return fmaf(qd, frac, qy) * QINV;
    };

    const int n4 = n >> 2;
    const int stride = MAIN_GRID * MAIN_THREADS;
    const float4* __restrict__ x4 = (const float4*)x;
    float4* __restrict__ o4 = (float4*)out;

    int i = blockIdx.x * MAIN_THREADS + threadIdx.x;

    // 2x unrolled grid-stride: 8 independent elements in flight
    for (; i + stride < n4; i += 2 * stride) {
        float4 va = x4[i];
        float4 vb = x4[i + stride];
        float4 oa, ob;
        oa.x = eval(va.x);  oa.y = eval(va.y);
        oa.z = eval(va.z);  oa.w = eval(va.w);
        ob.x = eval(vb.x);  ob.y = eval(vb.y);
        ob.z = eval(vb.z);  ob.w = eval(vb.w);
        o4[i] = oa;
        o4[i + stride] = ob;
    }
    for (; i < n4; i += stride) {
        float4 v = x4[i];
        float4 o;
        o.x = eval(v.x);  o.y = eval(v.y);
        o.z = eval(v.z);  o.w = eval(v.w);
        o4[i] = o;
    }

    const int base = n4 << 2;   // tail (n % 4)
    if (blockIdx.x == 0) {
        for (int j = base + threadIdx.x; j < n; j += MAIN_THREADS)
            out[j] = eval(x[j]);
    }
}

extern "C" void kernel_launch(void* const* d_in, const int* in_sizes, int n_in,
                              void* d_out, int out_size) {
    const float* x  = (const float*)d_in[0];
    const float* ri = (const float*)d_in[1];
    const float* ro = (const float*)d_in[2];
    float* out      = (float*)d_out;
    const int n = in_sizes[0];
    const int R = in_sizes[1];

    build_pack<<<KBUCK / 128, 128>>>(ri, ro, R);
    cudaFuncSetAttribute(calib_main, cudaFuncAttributeMaxDynamicSharedMemorySize,
                         SMEM_BYTES);
    calib_main<<<MAIN_GRID, MAIN_THREADS, SMEM_BYTES>>>(x, ri, out, n, R);
}

// round 12
// speedup vs baseline: 1.6072x; 1.1537x over previous
#include <cuda_runtime.h>

// CalibrationLayer R12: shared-search build + full-occupancy streamer.
//
//  k1 build_pack: each block stages ri (16KB) into shared; one thread per
//     bucket runs two 12-step binary searches IN SHARED (29-cyc LDS chain vs
//     ~250-cyc L2 chain), quantizes, packs
//     rec(b) = (round(ylo*65535)<<16) | (qy(b+1)-qy(b))  -> g_tab.
//  k2 calib_main: CTA copies g_tab (57KB, L2-hot) into shared; branchless
//     frac eval. 512 thr x 4 CTAs/SM = 2048 thr/SM (4x(57344+1024) = 228KB
//     carveout exactly); <=32 regs via launch bounds, no manual unroll
//     (float4 body already gives 4-deep MLP; occupancy hides the rest).
// Accuracy: chord dev ~5e-6 + quant 8e-6 abs << 1e-3 tolerance; fb-clamp
// makes both end-clamps exact (edge values = ro endpoints).

#define KBUCK   14336
#define QS      65535.0f
#define QINV    (1.0f / 65535.0f)
#define RMAX    4096

#define BUILD_THREADS 512

#define MAIN_THREADS 512
#define MAIN_CTAS    4
#define MAIN_GRID    (148 * MAIN_CTAS)
#define SMEM_BYTES   (KBUCK * 4)

__device__ unsigned int g_tab[KBUCK];

// ---- kernel 1: build + pack, binary search in shared ----
__global__ __launch_bounds__(BUILD_THREADS)
void build_pack(const float* __restrict__ ri,
                const float* __restrict__ ro, int R) {
    __shared__ float sri[RMAX];
    const int rcap = (R < RMAX) ? R : RMAX;
    for (int i = threadIdx.x; i < rcap; i += BUILD_THREADS)
        sri[i] = ri[i];
    __syncthreads();

    const float lo = sri[0];
    const float hi = sri[R - 1];
    const float w  = (hi - lo) / (float)KBUCK;

    auto edge_val = [&](int e) -> float {
        float ex = fmaf((float)e, w, lo);
        int a = 0, b = R - 1;
        while (b - a > 1) {                    // find a: sri[a] <= ex < sri[a+1]
            int m = (a + b) >> 1;
            if (sri[m] <= ex) a = m; else b = m;
        }
        float xt = sri[a], xp = sri[a + 1];
        float yt = __ldg(ro + a), yp = __ldg(ro + a + 1);
        return yt + (yp - yt) * __fdividef(ex - xt, xp - xt);
    };

    int bk = blockIdx.x * BUILD_THREADS + threadIdx.x;
    if (bk < KBUCK) {
        float yl = edge_val(bk);
        float yh = edge_val(bk + 1);
        int ql = min(max(__float2int_rn(yl * QS), 0), 65535);
        int qh = min(max(__float2int_rn(yh * QS), 0), 65535);
        g_tab[bk] = ((unsigned int)ql << 16) | (unsigned int)(qh - ql);
    }
}

// ---- kernel 2: streamer ----
extern __shared__ unsigned int tb[];

__global__ __launch_bounds__(MAIN_THREADS, MAIN_CTAS)
void calib_main(const float* __restrict__ x,
                const float* __restrict__ ri,
                float* __restrict__ out,
                int n, int R) {
    // cooperative table load (coalesced, L2-hot: 7x LDG.128 per thread)
    {
        const uint4* __restrict__ src = (const uint4*)g_tab;
        uint4* __restrict__ dst = (uint4*)tb;
        #pragma unroll
        for (int k = 0; k < KBUCK / 4 / MAIN_THREADS; ++k)
            dst[k * MAIN_THREADS + threadIdx.x] = src[k * MAIN_THREADS + threadIdx.x];
    }
    __syncthreads();

    const float lo   = __ldg(&ri[0]);
    const float hi   = __ldg(&ri[R - 1]);
    const float invw = (float)KBUCK / (hi - lo);
    const float nglo = -lo * invw;
    const float fK   = (float)KBUCK;

    auto eval = [&](float xv) -> float {
        float fb = fmaf(xv, invw, nglo);
        fb = fminf(fmaxf(fb, 0.0f), fK);          // end-clamps via edge values
        int b = (int)fb;                          // trunc == floor (fb >= 0)
        b = min(b, KBUCK - 1);                    // fb == K -> top bucket, frac=1
        unsigned int rec = tb[b];                 // LDS.32
        float frac = fb - (float)b;
        float qy = (float)(rec >> 16);
        float qd = (float)(rec & 0xFFFFu);
        return fmaf(qd, frac, qy) * QINV;
    };

    const int n4 = n >> 2;
    const int stride = MAIN_GRID * MAIN_THREADS;
    const float4* __restrict__ x4 = (const float4*)x;
    float4* __restrict__ o4 = (float4*)out;

    for (int i = blockIdx.x * MAIN_THREADS + threadIdx.x; i < n4; i += stride) {
        float4 v = x4[i];
        float4 o;
        o.x = eval(v.x);
        o.y = eval(v.y);
        o.z = eval(v.z);
        o.w = eval(v.w);
        o4[i] = o;
    }

    const int base = n4 << 2;   // tail (n % 4)
    if (blockIdx.x == 0) {
        for (int j = base + threadIdx.x; j < n; j += MAIN_THREADS)
            out[j] = eval(x[j]);
    }
}

extern "C" void kernel_launch(void* const* d_in, const int* in_sizes, int n_in,
                              void* d_out, int out_size) {
    const float* x  = (const float*)d_in[0];
    const float* ri = (const float*)d_in[1];
    const float* ro = (const float*)d_in[2];
    float* out      = (float*)d_out;
    const int n = in_sizes[0];
    const int R = in_sizes[1];

    build_pack<<<KBUCK / BUILD_THREADS, BUILD_THREADS>>>(ri, ro, R);
    cudaFuncSetAttribute(calib_main, cudaFuncAttributeMaxDynamicSharedMemorySize,
                         SMEM_BYTES);
    calib_main<<<MAIN_GRID, MAIN_THREADS, SMEM_BYTES>>>(x, ri, out, n, R);
}